// round 7
// baseline (speedup 1.0000x reference)
#include <cuda_runtime.h>
#include <cuda_bf16.h>
#include <math.h>

// Inputs (metadata order):
//   d_in[0]: node_ids      int32   [N_IDS]          (200,000)
//   d_in[1]: state_table   float32 [N_NODES, 1]     (1,000,000)
//   d_in[2]: memory_table  float32 [N_NODES, 128]   (128,000,000)
//   d_in[3]: W             float32 [1, 128]
//   d_in[4]: b             float32 [1]
// Output: concat(updated_table [N_NODES], is_updated [N_IDS]) float32

// ---------------------------------------------------------------------------
// Kernel 1: copy state_table -> out[0:n_nodes), vectorized float4.
// ---------------------------------------------------------------------------
__global__ void copy_state_kernel(const float4* __restrict__ src,
                                  float4* __restrict__ dst,
                                  int n4) {
    int i = blockIdx.x * blockDim.x + threadIdx.x;
    int stride = gridDim.x * blockDim.x;
    for (; i < n4; i += stride) dst[i] = src[i];
}

// ---------------------------------------------------------------------------
// Kernel 2: 8 nodes per warp, all memory front-batched, WITH register
// headroom. __launch_bounds__(256, 2) raises the per-thread register budget
// to ~128 so ptxas can keep all 8 row loads (8 x float4 = 32 regs) in flight
// simultaneously -> real per-warp MLP ~10 instead of the serialized ~2-4 we
// got at a 32-reg budget.
// ---------------------------------------------------------------------------
__global__ __launch_bounds__(256, 2) void state_update_kernel(
    const int*   __restrict__ node_ids,
    const float* __restrict__ state_table,
    const float* __restrict__ memory_table,
    const float* __restrict__ W,
    const float* __restrict__ b,
    float*       __restrict__ out,
    int n_ids, int n_nodes, int out_size)
{
    constexpr int NPW = 8;                          // nodes per warp
    int warp = (blockIdx.x * blockDim.x + threadIdx.x) >> 5;
    int lane = threadIdx.x & 31;
    int base = warp * NPW;
    if (base >= n_ids) return;

    // coalesced id fetch by lanes 0..7, then broadcast
    int myid = 0;
    bool owner = (lane < NPW) && (base + lane < n_ids);
    if (owner) myid = __ldg(node_ids + base + lane);

    int ids[NPW];
    #pragma unroll
    for (int j = 0; j < NPW; j++)
        ids[j] = __shfl_sync(0xffffffffu, myid, j);

    // independent scalar traffic first: state (owner lanes), bias, W (cached)
    float st   = owner ? __ldg(state_table + myid) : 0.0f;
    float bias = __ldg(b);
    float4 w   = __ldg(reinterpret_cast<const float4*>(W) + lane);

    // 8 independent 512B row loads — with the raised register budget these
    // all stay in flight before any consumption.
    float4 m[NPW];
    #pragma unroll
    for (int j = 0; j < NPW; j++)
        m[j] = __ldg(reinterpret_cast<const float4*>(
                   memory_table + (size_t)ids[j] * 128) + lane);

    float p[NPW];
    #pragma unroll
    for (int j = 0; j < NPW; j++)
        p[j] = m[j].x * w.x + m[j].y * w.y + m[j].z * w.z + m[j].w * w.w;

    // 8 interleaved butterfly reductions (sum ends up in every lane)
    #pragma unroll
    for (int off = 16; off > 0; off >>= 1) {
        #pragma unroll
        for (int j = 0; j < NPW; j++)
            p[j] += __shfl_xor_sync(0xffffffffu, p[j], off);
    }

    if (owner) {
        float x     = p[lane] + bias;
        float delta = 1.0f / (1.0f + __expf(-x));
        float isup  = (st > 0.0f) ? 1.0f : 0.0f;
        float ns    = isup * delta
                    + (1.0f - isup) * (st + fminf(delta, 1.0f - st));
        out[myid] = ns;                          // scattered state write
        int oi = n_nodes + base + lane;          // coalesced is_updated write
        if (oi < out_size) out[oi] = isup;
    }
}

extern "C" void kernel_launch(void* const* d_in, const int* in_sizes, int n_in,
                              void* d_out, int out_size) {
    const int*   node_ids     = (const int*)  d_in[0];
    const float* state_table  = (const float*)d_in[1];
    const float* memory_table = (const float*)d_in[2];
    const float* W            = (const float*)d_in[3];
    const float* b            = (const float*)d_in[4];
    float*       out          = (float*)d_out;

    int n_ids   = in_sizes[0];
    int n_nodes = in_sizes[1];

    // 1) table copy (n_nodes = 1e6, divisible by 4)
    {
        int n4 = n_nodes >> 2;
        int threads = 256;
        int blocks  = (n4 + threads - 1) / threads;
        copy_state_kernel<<<blocks, threads>>>(
            (const float4*)state_table, (float4*)out, n4);
    }

    // 2) gather/update/scatter: 8 nodes per warp
    {
        int threads = 256;                        // 8 warps * 8 nodes = 64/block
        int nodes_per_block = (threads / 32) * 8;
        int blocks = (n_ids + nodes_per_block - 1) / nodes_per_block;
        state_update_kernel<<<blocks, threads>>>(
            node_ids, state_table, memory_table, W, b,
            out, n_ids, n_nodes, out_size);
    }
}